// round 3
// baseline (speedup 1.0000x reference)
#include <cuda_runtime.h>

#define B_      16384
#define D_      256
#define NSTEPS_ 5
#define BD      (B_*D_)

// Persistent state (re-initialized on every kernel_launch -> deterministic).
__device__ __align__(16) float g_x  [BD];   // current binary state (0/1 as f32)
__device__ __align__(16) float g_xa [BD];   // auxiliary state
__device__ __align__(16) float g_vx [BD];   // x @ W   (carried across steps)
__device__ __align__(16) float g_xd [BD];   // proposal x_delta
__device__ __align__(16) float g_vxd[BD];   // x_delta @ W
__device__ __align__(16) float g_p  [BD];   // forward flip probability (consistent reuse)

// ---------------------------------------------------------------------------
// flip probability, mirroring reference op order exactly.
// s = -(2x-1) = +-1 exactly, so the *s multiplications are exact.
__device__ __forceinline__ float flip_p(float vx, float bv, float ga, float s) {
    float d  = ((vx + bv) * s) * 0.5f;     // diff_fn / TEMP   (TEMP=2: exact scale)
    float gm = d - (ga * 0.5f) * s;        // - (ga/TEMP) * -(2x-1)
    float t  = gm - 2.5f;                  // - 1/(2*ALPHA)
    return 1.0f / (1.0f + expf(-t));
}

__global__ void kinit(const float* __restrict__ x_in, const float* __restrict__ xa_in) {
    int i = blockIdx.x * blockDim.x + threadIdx.x;
    if (i < BD) { g_x[i] = x_in[i]; g_xa[i] = xa_in[i]; }
}

// First proposal (step 0) — thereafter fused into phase2.
__global__ void phase1(const float* __restrict__ rr_s, const float* __restrict__ bvec) {
    int i = blockIdx.x * blockDim.x + threadIdx.x;
    if (i >= BD) return;
    float x  = g_x[i];
    float s  = 1.0f - 2.0f * x;
    float ga = (x - g_xa[i]) / 1.0e4f;
    float p  = flip_p(g_vx[i], bvec[i & 255], ga, s);
    float ind = (rr_s[i] < p) ? 1.0f : 0.0f;
    g_xd[i] = x + ind * s;                 // exact flip in {0,1}
    g_p[i]  = p;
}

// ---------------------------------------------------------------------------
// GEMM: C = A[16384,256] @ W[256,256], f32, fma.rn.f32x2, chunked accumulators
// (flush per 32-K chunk via add.rn.f32x2 -> ~3x lower accumulation noise).
#define TM 32
#define KC 32
__global__ __launch_bounds__(256) void gemm32(const float* __restrict__ Wm, int use_xd) {
    const float* __restrict__ A = use_xd ? g_xd : g_x;
    float*       __restrict__ C = use_xd ? g_vxd : g_vx;

    __shared__ float As[KC][TM + 1];
    __shared__ float Ws[KC][256];

    const int t  = threadIdx.x;
    const int tc = t & 31;
    const int tr = t >> 5;
    const int m0 = blockIdx.x * TM;

    unsigned long long acc[4][4];
    #pragma unroll
    for (int r = 0; r < 4; r++)
        #pragma unroll
        for (int j = 0; j < 4; j++) acc[r][j] = 0ull;

    for (int k0 = 0; k0 < 256; k0 += KC) {
        #pragma unroll
        for (int i = 0; i < 4; i++) {
            int idx = t + 256 * i;
            int m = idx >> 5, kk = idx & 31;
            As[kk][m] = A[(size_t)(m0 + m) * 256 + k0 + kk];
        }
        #pragma unroll
        for (int i = 0; i < 8; i++) {
            int idx = t + 256 * i;
            int kk = idx >> 6, n4 = idx & 63;
            *(float4*)&Ws[kk][n4 * 4] =
                *(const float4*)&Wm[(size_t)(k0 + kk) * 256 + n4 * 4];
        }
        __syncthreads();

        unsigned long long cacc[4][4];
        #pragma unroll
        for (int r = 0; r < 4; r++)
            #pragma unroll
            for (int j = 0; j < 4; j++) cacc[r][j] = 0ull;

        #pragma unroll
        for (int kk = 0; kk < KC; kk++) {
            unsigned long long w[4];
            #pragma unroll
            for (int j = 0; j < 4; j++)
                w[j] = *(const unsigned long long*)&Ws[kk][2 * (tc + 32 * j)];
            #pragma unroll
            for (int r = 0; r < 4; r++) {
                float a = As[kk][tr * 4 + r];
                unsigned long long a2;
                asm("mov.b64 %0, {%1,%1};" : "=l"(a2) : "f"(a));
                #pragma unroll
                for (int j = 0; j < 4; j++)
                    asm("fma.rn.f32x2 %0, %1, %2, %0;"
                        : "+l"(cacc[r][j]) : "l"(a2), "l"(w[j]));
            }
        }
        #pragma unroll
        for (int r = 0; r < 4; r++)
            #pragma unroll
            for (int j = 0; j < 4; j++)
                asm("add.rn.f32x2 %0, %0, %1;" : "+l"(acc[r][j]) : "l"(cacc[r][j]));
        __syncthreads();
    }

    #pragma unroll
    for (int r = 0; r < 4; r++) {
        size_t row = m0 + tr * 4 + r;
        #pragma unroll
        for (int j = 0; j < 4; j++)
            *(unsigned long long*)&C[row * 256 + 2 * (tc + 32 * j)] = acc[r][j];
    }
}

// ---------------------------------------------------------------------------
__device__ __forceinline__ double wsumd(double v) {
    #pragma unroll
    for (int off = 16; off; off >>= 1) v += __shfl_xor_sync(0xffffffffu, v, off, 32);
    return v;
}

// Phase 2 (fused with next phase1): one warp per row.
// Per-element terms in f32 (mirroring reference ops), accumulated in f64 so
// our log-acceptance is exact; MH accept; in-place select; next proposal.
__global__ __launch_bounds__(256) void phase2(const float* __restrict__ noise_s,
                                              const float* __restrict__ u_s,
                                              const float* __restrict__ rr_next,
                                              const float* __restrict__ bvec,
                                              float* __restrict__ out, int last) {
    int gwarp = (blockIdx.x * blockDim.x + threadIdx.x) >> 5;   // row
    int lane  = threadIdx.x & 31;
    if (gwarp >= B_) return;

    float xv[8], xav[8], xdv[8], xdav[8], vxv[8], vxdv[8], bvv[8];
    double q = 0.0;

    #pragma unroll
    for (int j = 0; j < 8; j++) {
        int d = lane + 32 * j;
        size_t i = (size_t)gwarp * 256 + d;
        float x   = g_x[i];
        float xa  = g_xa[i];
        float vx  = g_vx[i];
        float vxd = g_vxd[i];
        float xd  = g_xd[i];
        float p   = g_p[i];
        float nz  = noise_s[i];
        float bv  = bvec[d];

        float ga  = (x - xa) / 1.0e4f;
        float ind = (x != xd) ? 1.0f : 0.0f;
        float xda = (xa + 0.25f * ga) + 0.70710678118654752f * nz;

        float s2  = 1.0f - 2.0f * xd;
        float ga2 = (xd - xda) / 1.0e4f;
        float p2  = flip_p(vxd, bv, ga2, s2);

        // lp_reverse - lp_forward (per-element f32 logs, f64 sum)
        float a1 = (ind != 0.0f) ? (p  + 1e-10f) : ((1.0f - p)  + 1e-10f);
        float a2 = (ind != 0.0f) ? (p2 + 1e-10f) : ((1.0f - p2) + 1e-10f);
        q += (double)logf(a2) - (double)logf(a1);

        // m_term: [0.5*vxd*xd + bv*xd - dn^2/(2 ETA)] - [0.5*vx*x + bv*x - dc^2/(2 ETA)]
        float dc = x  - xa;  float dc2 = dc * dc;
        float dn = xd - xda; float dn2 = dn * dn;
        q += 0.5 * (double)(vxd * xd) + (double)(bv * xd) - (double)dn2 / 2.0e4;
        q -= 0.5 * (double)(vx  * x ) + (double)(bv * x ) - (double)dc2 / 2.0e4;

        // add_rev - add_fwd, both /(-2*alpha_a) = *(-1)  =>  + (ff^2 - fr^2)
        float ff = xda - (xa + 0.25f * ga);
        float fr = xa  - (xda + 0.25f * ga2);
        q += (double)(ff * ff) - (double)(fr * fr);

        xv[j]=x; xav[j]=xa; xdv[j]=xd; xdav[j]=xda; vxv[j]=vx; vxdv[j]=vxd; bvv[j]=bv;
    }

    double la = wsumd(q);
    int accept = la > log((double)u_s[gwarp]);

    if (last) {
        #pragma unroll
        for (int j = 0; j < 8; j++) {
            size_t i = (size_t)gwarp * 256 + lane + 32 * j;
            out[i]      = accept ? xdv[j]  : xv[j];
            out[BD + i] = accept ? xdav[j] : xav[j];
        }
        return;
    }

    // Select new state + fused next proposal.
    #pragma unroll
    for (int j = 0; j < 8; j++) {
        size_t i = (size_t)gwarp * 256 + lane + 32 * j;
        float xn  = accept ? xdv[j]  : xv[j];
        float xan = accept ? xdav[j] : xav[j];
        float vxn = accept ? vxdv[j] : vxv[j];
        if (accept) { g_x[i] = xn; g_xa[i] = xan; g_vx[i] = vxn; }

        float s  = 1.0f - 2.0f * xn;
        float ga = (xn - xan) / 1.0e4f;
        float p  = flip_p(vxn, bvv[j], ga, s);
        float ind = (rr_next[i] < p) ? 1.0f : 0.0f;
        g_xd[i] = xn + ind * s;
        g_p[i]  = p;
    }
}

// ---------------------------------------------------------------------------
extern "C" void kernel_launch(void* const* d_in, const int* in_sizes, int n_in,
                              void* d_out, int out_size) {
    (void)in_sizes; (void)n_in; (void)out_size;
    const float* x_in  = (const float*)d_in[0];
    const float* xa_in = (const float*)d_in[1];
    const float* Wm    = (const float*)d_in[2];
    const float* bvec  = (const float*)d_in[3];
    const float* rr    = (const float*)d_in[4];
    const float* noise = (const float*)d_in[5];
    const float* u     = (const float*)d_in[6];
    float* out = (float*)d_out;

    kinit<<<BD / 256, 256>>>(x_in, xa_in);
    gemm32<<<B_ / TM, 256>>>(Wm, 0);                 // g_vx = x @ W
    phase1<<<BD / 256, 256>>>(rr, bvec);             // proposal for step 0
    for (int s = 0; s < NSTEPS_; s++) {
        gemm32<<<B_ / TM, 256>>>(Wm, 1);             // g_vxd = x_delta @ W
        int lastf = (s == NSTEPS_ - 1);
        phase2<<<B_ / 8, 256>>>(noise + (size_t)s * BD, u + (size_t)s * B_,
                                lastf ? (const float*)d_in[4]   // unused when last
                                      : rr + (size_t)(s + 1) * BD,
                                bvec, out, lastf);
    }
}

// round 4
// speedup vs baseline: 2.3403x; 2.3403x over previous
#include <cuda_runtime.h>

#define B_      16384
#define D_      256
#define NSTEPS_ 5
#define BD      (B_*D_)

// Persistent state (re-initialized on every kernel_launch -> deterministic).
__device__ __align__(16) float g_x  [BD];   // current binary state (0/1 as f32)
__device__ __align__(16) float g_xa [BD];   // auxiliary state
__device__ __align__(16) float g_vx [BD];   // x @ W   (carried across steps)
__device__ __align__(16) float g_xd [BD];   // proposal x_delta
__device__ __align__(16) float g_vxd[BD];   // x_delta @ W
__device__ __align__(16) float g_p  [BD];   // forward flip probability (consistent reuse)

// ---------------------------------------------------------------------------
// flip probability, bit-identical to the R3 version that produced 0 flips.
__device__ __forceinline__ float flip_p(float vx, float bv, float ga, float s) {
    float d  = ((vx + bv) * s) * 0.5f;     // diff_fn / TEMP
    float gm = d - (ga * 0.5f) * s;        // - (ga/TEMP) * -(2x-1)
    float t  = gm - 2.5f;                  // - 1/(2*ALPHA)
    return 1.0f / (1.0f + expf(-t));
}

__global__ void kinit(const float* __restrict__ x_in, const float* __restrict__ xa_in) {
    int i = blockIdx.x * blockDim.x + threadIdx.x;
    if (i < BD) { g_x[i] = x_in[i]; g_xa[i] = xa_in[i]; }
}

// First proposal (step 0) — thereafter fused into phase2.
__global__ void phase1(const float* __restrict__ rr_s, const float* __restrict__ bvec) {
    int i = blockIdx.x * blockDim.x + threadIdx.x;
    if (i >= BD) return;
    float x  = g_x[i];
    float s  = 1.0f - 2.0f * x;
    float ga = (x - g_xa[i]) / 1.0e4f;
    float p  = flip_p(g_vx[i], bvec[i & 255], ga, s);
    float ind = (rr_s[i] < p) ? 1.0f : 0.0f;
    g_xd[i] = x + ind * s;                 // exact flip in {0,1}
    g_p[i]  = p;
}

// ---------------------------------------------------------------------------
// GEMM: C = A[16384,256] @ W[256,256], f32, fma.rn.f32x2, chunked accumulators.
// Register-staged prefetch pipeline: global loads of chunk k+1 overlap compute
// of chunk k. Accumulation order is bit-identical to the R3 version.
#define TM 32
#define KC 32
__global__ __launch_bounds__(256) void gemm32(const float* __restrict__ Wm, int use_xd) {
    const float* __restrict__ A = use_xd ? g_xd : g_x;
    float*       __restrict__ C = use_xd ? g_vxd : g_vx;

    __shared__ float As[KC][TM + 1];
    __shared__ float Ws[KC][256];

    const int t  = threadIdx.x;
    const int tc = t & 31;
    const int tr = t >> 5;
    const int m0 = blockIdx.x * TM;

    // Per-thread load coordinates (constant across chunks).
    int am[4], ak[4], wk[8], wn4[8];
    #pragma unroll
    for (int i = 0; i < 4; i++) { int idx = t + 256 * i; am[i] = idx >> 5; ak[i] = idx & 31; }
    #pragma unroll
    for (int i = 0; i < 8; i++) { int idx = t + 256 * i; wk[i] = idx >> 6; wn4[i] = idx & 63; }

    unsigned long long acc[4][4];
    #pragma unroll
    for (int r = 0; r < 4; r++)
        #pragma unroll
        for (int j = 0; j < 4; j++) acc[r][j] = 0ull;

    float  ra[4];
    float4 rw[8];
    // Prologue: load chunk 0 into registers.
    #pragma unroll
    for (int i = 0; i < 4; i++) ra[i] = __ldg(&A[(size_t)(m0 + am[i]) * 256 + ak[i]]);
    #pragma unroll
    for (int i = 0; i < 8; i++) rw[i] = __ldg((const float4*)&Wm[(size_t)wk[i] * 256 + wn4[i] * 4]);

    #pragma unroll 1
    for (int c = 0; c < 256 / KC; c++) {
        __syncthreads();
        #pragma unroll
        for (int i = 0; i < 4; i++) As[ak[i]][am[i]] = ra[i];
        #pragma unroll
        for (int i = 0; i < 8; i++) *(float4*)&Ws[wk[i]][wn4[i] * 4] = rw[i];
        __syncthreads();

        if (c + 1 < 256 / KC) {
            int k0 = (c + 1) * KC;
            #pragma unroll
            for (int i = 0; i < 4; i++) ra[i] = __ldg(&A[(size_t)(m0 + am[i]) * 256 + k0 + ak[i]]);
            #pragma unroll
            for (int i = 0; i < 8; i++) rw[i] = __ldg((const float4*)&Wm[(size_t)(k0 + wk[i]) * 256 + wn4[i] * 4]);
        }

        unsigned long long cacc[4][4];
        #pragma unroll
        for (int r = 0; r < 4; r++)
            #pragma unroll
            for (int j = 0; j < 4; j++) cacc[r][j] = 0ull;

        #pragma unroll
        for (int kk = 0; kk < KC; kk++) {
            unsigned long long w[4];
            #pragma unroll
            for (int j = 0; j < 4; j++)
                w[j] = *(const unsigned long long*)&Ws[kk][2 * (tc + 32 * j)];
            #pragma unroll
            for (int r = 0; r < 4; r++) {
                float a = As[kk][tr * 4 + r];
                unsigned long long a2;
                asm("mov.b64 %0, {%1,%1};" : "=l"(a2) : "f"(a));
                #pragma unroll
                for (int j = 0; j < 4; j++)
                    asm("fma.rn.f32x2 %0, %1, %2, %0;"
                        : "+l"(cacc[r][j]) : "l"(a2), "l"(w[j]));
            }
        }
        #pragma unroll
        for (int r = 0; r < 4; r++)
            #pragma unroll
            for (int j = 0; j < 4; j++)
                asm("add.rn.f32x2 %0, %0, %1;" : "+l"(acc[r][j]) : "l"(cacc[r][j]));
    }

    #pragma unroll
    for (int r = 0; r < 4; r++) {
        size_t row = m0 + tr * 4 + r;
        #pragma unroll
        for (int j = 0; j < 4; j++)
            *(unsigned long long*)&C[row * 256 + 2 * (tc + 32 * j)] = acc[r][j];
    }
}

// ---------------------------------------------------------------------------
__device__ __forceinline__ double wsumd(double v) {
    #pragma unroll
    for (int off = 16; off; off >>= 1) v += __shfl_xor_sync(0xffffffffu, v, off, 32);
    return v;
}

// Phase 2 (fused with next phase1): one warp per row.
// Per-element terms in f32 (same groupings as the passing R3), combined into a
// single f32 value per element, accumulated in f64 (2 f64 ops/element instead
// of ~58 incl. two DDIVs). MH accept; in-place select; next proposal.
__global__ __launch_bounds__(256) void phase2(const float* __restrict__ noise_s,
                                              const float* __restrict__ u_s,
                                              const float* __restrict__ rr_next,
                                              const float* __restrict__ bvec,
                                              float* __restrict__ out, int last) {
    int gwarp = (blockIdx.x * blockDim.x + threadIdx.x) >> 5;   // row
    int lane  = threadIdx.x & 31;
    if (gwarp >= B_) return;

    float xdv[8], xdav[8], vxdv[8], bvv[8];
    double q = 0.0;

    #pragma unroll
    for (int j = 0; j < 8; j++) {
        int d = lane + 32 * j;
        size_t i = (size_t)gwarp * 256 + d;
        float x   = g_x[i];
        float xa  = g_xa[i];
        float vx  = g_vx[i];
        float vxd = g_vxd[i];
        float xd  = g_xd[i];
        float p   = g_p[i];
        float nz  = noise_s[i];
        float bv  = bvec[d];

        float ga  = (x - xa) / 1.0e4f;
        float ind = (x != xd) ? 1.0f : 0.0f;
        float xda = (xa + 0.25f * ga) + 0.70710678118654752f * nz;

        float s2  = 1.0f - 2.0f * xd;
        float ga2 = (xd - xda) / 1.0e4f;
        float p2  = flip_p(vxd, bv, ga2, s2);

        // lp_reverse - lp_forward
        float a1 = (ind != 0.0f) ? (p  + 1e-10f) : ((1.0f - p)  + 1e-10f);
        float a2 = (ind != 0.0f) ? (p2 + 1e-10f) : ((1.0f - p2) + 1e-10f);
        float t_log = logf(a2) - logf(a1);

        // m_term: [E(xd) - dn^2/(2 ETA)] - [E(x) - dc^2/(2 ETA)]
        float dc = x  - xa;
        float dn = xd - xda;
        float t_m = ((0.5f * (vxd * xd) + bv * xd) - (dn * dn) * 5e-5f)
                  - ((0.5f * (vx  * x ) + bv * x ) - (dc * dc) * 5e-5f);

        // add_rev - add_fwd (both carry /(-2*alpha_a) = *(-1)) => + (ff^2 - fr^2)
        float ff = xda - (xa + 0.25f * ga);
        float fr = xa  - (xda + 0.25f * ga2);
        float t_q = ff * ff - fr * fr;

        q += (double)(t_log + t_m + t_q);

        xdv[j] = xd; xdav[j] = xda; vxdv[j] = vxd; bvv[j] = bv;
    }

    double la = wsumd(q);
    int accept = la > log((double)u_s[gwarp]);

    if (last) {
        #pragma unroll
        for (int j = 0; j < 8; j++) {
            size_t i = (size_t)gwarp * 256 + lane + 32 * j;
            out[i]      = accept ? xdv[j]  : g_x[i];
            out[BD + i] = accept ? xdav[j] : g_xa[i];
        }
        return;
    }

    // Select new state + fused next proposal (reject path reloads from L1-hot state).
    #pragma unroll
    for (int j = 0; j < 8; j++) {
        size_t i = (size_t)gwarp * 256 + lane + 32 * j;
        float xn  = accept ? xdv[j]  : g_x[i];
        float xan = accept ? xdav[j] : g_xa[i];
        float vxn = accept ? vxdv[j] : g_vx[i];
        if (accept) { g_x[i] = xn; g_xa[i] = xan; g_vx[i] = vxn; }

        float s  = 1.0f - 2.0f * xn;
        float ga = (xn - xan) / 1.0e4f;
        float p  = flip_p(vxn, bvv[j], ga, s);
        float ind = (rr_next[i] < p) ? 1.0f : 0.0f;
        g_xd[i] = xn + ind * s;
        g_p[i]  = p;
    }
}

// ---------------------------------------------------------------------------
extern "C" void kernel_launch(void* const* d_in, const int* in_sizes, int n_in,
                              void* d_out, int out_size) {
    (void)in_sizes; (void)n_in; (void)out_size;
    const float* x_in  = (const float*)d_in[0];
    const float* xa_in = (const float*)d_in[1];
    const float* Wm    = (const float*)d_in[2];
    const float* bvec  = (const float*)d_in[3];
    const float* rr    = (const float*)d_in[4];
    const float* noise = (const float*)d_in[5];
    const float* u     = (const float*)d_in[6];
    float* out = (float*)d_out;

    kinit<<<BD / 256, 256>>>(x_in, xa_in);
    gemm32<<<B_ / TM, 256>>>(Wm, 0);                 // g_vx = x @ W
    phase1<<<BD / 256, 256>>>(rr, bvec);             // proposal for step 0
    for (int s = 0; s < NSTEPS_; s++) {
        gemm32<<<B_ / TM, 256>>>(Wm, 1);             // g_vxd = x_delta @ W
        int lastf = (s == NSTEPS_ - 1);
        phase2<<<B_ / 8, 256>>>(noise + (size_t)s * BD, u + (size_t)s * B_,
                                lastf ? (const float*)d_in[4]   // unused when last
                                      : rr + (size_t)(s + 1) * BD,
                                bvec, out, lastf);
    }
}

// round 6
// speedup vs baseline: 2.8746x; 1.2283x over previous
#include <cuda_runtime.h>

#define B_      16384
#define D_      256
#define NSTEPS_ 5
#define BD      (B_*D_)

// Persistent state (re-initialized on every kernel_launch -> deterministic).
__device__ __align__(16) float g_x  [BD];   // current binary state (0/1 as f32)
__device__ __align__(16) float g_xa [BD];   // auxiliary state
__device__ __align__(16) float g_vx [BD];   // x @ W   (carried across steps)
__device__ __align__(16) float g_xd [BD];   // proposal x_delta
__device__ __align__(16) float g_vxd[BD];   // x_delta @ W
__device__ __align__(16) float g_p  [BD];   // forward flip probability

// ---------------------------------------------------------------------------
// flip probability, bit-identical to the version that produced 0 flips.
__device__ __forceinline__ float flip_p(float vx, float bv, float ga, float s) {
    float d  = ((vx + bv) * s) * 0.5f;     // diff_fn / TEMP
    float gm = d - (ga * 0.5f) * s;        // - (ga/TEMP) * -(2x-1)
    float t  = gm - 2.5f;                  // - 1/(2*ALPHA)
    return 1.0f / (1.0f + expf(-t));
}

__global__ void kinit(const float* __restrict__ x_in, const float* __restrict__ xa_in) {
    int i = blockIdx.x * blockDim.x + threadIdx.x;
    if (i < BD) { g_x[i] = x_in[i]; g_xa[i] = xa_in[i]; }
}

// First proposal (step 0) — thereafter fused into phase2.
__global__ void phase1(const float* __restrict__ rr_s, const float* __restrict__ bvec) {
    int i = blockIdx.x * blockDim.x + threadIdx.x;
    if (i >= BD) return;
    float x  = g_x[i];
    float s  = 1.0f - 2.0f * x;
    float ga = (x - g_xa[i]) / 1.0e4f;
    float p  = flip_p(g_vx[i], bvec[i & 255], ga, s);
    float ind = (rr_s[i] < p) ? 1.0f : 0.0f;
    g_xd[i] = x + ind * s;
    g_p[i]  = p;
}

// ---------------------------------------------------------------------------
// GEMM: C = A[16384,256] @ W[256,256], f32, fma.rn.f32x2.
// cp.async double-buffered smem (16-row chunks); accumulation order (32-k
// chunked cacc flushed via add.rn.f32x2) is bit-identical to the passing R3/R4.
#define TM  32
#define KCH 16
__global__ __launch_bounds__(256) void gemm32(const float* __restrict__ Wm, int use_xd) {
    const float* __restrict__ A = use_xd ? g_xd : g_x;
    float*       __restrict__ C = use_xd ? g_vxd : g_vx;

    __shared__ float As[2][KCH][TM + 1];
    __shared__ float Ws[2][KCH][256];

    const int t  = threadIdx.x;
    const int tc = t & 31;
    const int tr = t >> 5;
    const int m0 = blockIdx.x * TM;

    auto load_chunk = [&](int c, int buf) {
        int k0 = c * KCH;
        #pragma unroll
        for (int i = 0; i < 2; i++) {               // A: 32x16 floats, 4B each
            int e = t + 256 * i;
            int m = e >> 4, kk = e & 15;
            unsigned dst = (unsigned)__cvta_generic_to_shared(&As[buf][kk][m]);
            const float* src = &A[(size_t)(m0 + m) * 256 + k0 + kk];
            asm volatile("cp.async.ca.shared.global [%0], [%1], 4;" :: "r"(dst), "l"(src));
        }
        #pragma unroll
        for (int i = 0; i < 4; i++) {               // W: 16x256 floats, 16B each
            int idx = t + 256 * i;
            int kk = idx >> 6, n4 = idx & 63;
            unsigned dst = (unsigned)__cvta_generic_to_shared(&Ws[buf][kk][n4 * 4]);
            const float* src = &Wm[(size_t)(k0 + kk) * 256 + n4 * 4];
            asm volatile("cp.async.ca.shared.global [%0], [%1], 16;" :: "r"(dst), "l"(src));
        }
        asm volatile("cp.async.commit_group;");
    };

    unsigned long long acc[4][4], cacc[4][4];
    #pragma unroll
    for (int r = 0; r < 4; r++)
        #pragma unroll
        for (int j = 0; j < 4; j++) acc[r][j] = 0ull;

    load_chunk(0, 0);

    #pragma unroll 1
    for (int c = 0; c < 256 / KCH; c++) {
        if (c + 1 < 256 / KCH) {
            load_chunk(c + 1, (c + 1) & 1);
            asm volatile("cp.async.wait_group 1;");
        } else {
            asm volatile("cp.async.wait_group 0;");
        }
        __syncthreads();

        const int buf = c & 1;
        if ((c & 1) == 0) {
            #pragma unroll
            for (int r = 0; r < 4; r++)
                #pragma unroll
                for (int j = 0; j < 4; j++) cacc[r][j] = 0ull;
        }

        #pragma unroll
        for (int kk = 0; kk < KCH; kk++) {
            unsigned long long w[4];
            #pragma unroll
            for (int j = 0; j < 4; j++)
                w[j] = *(const unsigned long long*)&Ws[buf][kk][2 * (tc + 32 * j)];
            #pragma unroll
            for (int r = 0; r < 4; r++) {
                float a = As[buf][kk][tr * 4 + r];
                unsigned long long a2;
                asm("mov.b64 %0, {%1,%1};" : "=l"(a2) : "f"(a));
                #pragma unroll
                for (int j = 0; j < 4; j++)
                    asm("fma.rn.f32x2 %0, %1, %2, %0;"
                        : "+l"(cacc[r][j]) : "l"(a2), "l"(w[j]));
            }
        }

        if (c & 1) {
            #pragma unroll
            for (int r = 0; r < 4; r++)
                #pragma unroll
                for (int j = 0; j < 4; j++)
                    asm("add.rn.f32x2 %0, %0, %1;" : "+l"(acc[r][j]) : "l"(cacc[r][j]));
        }
        __syncthreads();
    }

    #pragma unroll
    for (int r = 0; r < 4; r++) {
        size_t row = m0 + tr * 4 + r;
        #pragma unroll
        for (int j = 0; j < 4; j++)
            *(unsigned long long*)&C[row * 256 + 2 * (tc + 32 * j)] = acc[r][j];
    }
}

// ---------------------------------------------------------------------------
__device__ __forceinline__ double wsumd(double v) {
    #pragma unroll
    for (int off = 16; off; off >>= 1) v += __shfl_xor_sync(0xffffffffu, v, off, 32);
    return v;
}

// Phase 2 (fused next proposal): one warp per row, lane owns 8 contiguous
// elements (float4 I/O). Per-element f32 terms (same groupings/order as the
// passing rounds) combined to one f32, accumulated in f64. p_next reuses p2
// (accept) or the stored g_p (reject) — bit-identical to recomputation.
__global__ __launch_bounds__(256) void phase2(const float* __restrict__ noise_s,
                                              const float* __restrict__ u_s,
                                              const float* __restrict__ rr_next,
                                              const float* __restrict__ bvec,
                                              float* __restrict__ out, int last) {
    int gwarp = (blockIdx.x * blockDim.x + threadIdx.x) >> 5;   // row
    int lane  = threadIdx.x & 31;
    if (gwarp >= B_) return;
    size_t base = (size_t)gwarp * 256 + lane * 8;
    int    dbase = lane * 8;

    float xv[8], xav[8], vxv[8], vxdv[8], xdv[8], pv[8], nzv[8], bvv[8];
    #pragma unroll
    for (int h = 0; h < 2; h++) {
        *(float4*)&xv  [4*h] = __ldg((const float4*)&g_x  [base + 4*h]);
        *(float4*)&xav [4*h] = __ldg((const float4*)&g_xa [base + 4*h]);
        *(float4*)&vxv [4*h] = __ldg((const float4*)&g_vx [base + 4*h]);
        *(float4*)&vxdv[4*h] = __ldg((const float4*)&g_vxd[base + 4*h]);
        *(float4*)&xdv [4*h] = __ldg((const float4*)&g_xd [base + 4*h]);
        *(float4*)&pv  [4*h] = __ldg((const float4*)&g_p  [base + 4*h]);
        *(float4*)&nzv [4*h] = __ldg((const float4*)&noise_s[base + 4*h]);
        *(float4*)&bvv [4*h] = __ldg((const float4*)&bvec [dbase + 4*h]);
    }

    float xdav[8], p2v[8];
    double q = 0.0;

    #pragma unroll
    for (int j = 0; j < 8; j++) {
        float x = xv[j], xa = xav[j], vx = vxv[j], vxd = vxdv[j];
        float xd = xdv[j], p = pv[j], nz = nzv[j], bv = bvv[j];

        float ga  = (x - xa) / 1.0e4f;
        float ind = (x != xd) ? 1.0f : 0.0f;
        float xda = (xa + 0.25f * ga) + 0.70710678118654752f * nz;

        float s2  = 1.0f - 2.0f * xd;
        float ga2 = (xd - xda) / 1.0e4f;
        float p2  = flip_p(vxd, bv, ga2, s2);

        float a1 = (ind != 0.0f) ? (p  + 1e-10f) : ((1.0f - p)  + 1e-10f);
        float a2 = (ind != 0.0f) ? (p2 + 1e-10f) : ((1.0f - p2) + 1e-10f);
        float t_log = __logf(a2) - __logf(a1);

        float dc = x  - xa;
        float dn = xd - xda;
        float t_m = ((0.5f * (vxd * xd) + bv * xd) - (dn * dn) * 5e-5f)
                  - ((0.5f * (vx  * x ) + bv * x ) - (dc * dc) * 5e-5f);

        float ff = xda - (xa + 0.25f * ga);
        float fr = xa  - (xda + 0.25f * ga2);
        float t_q = ff * ff - fr * fr;

        q += (double)(t_log + t_m + t_q);

        xdav[j] = xda; p2v[j] = p2;
    }

    double la = wsumd(q);
    int accept = la > log((double)__ldg(&u_s[gwarp]));

    if (last) {
        float o1[8], o2[8];
        #pragma unroll
        for (int j = 0; j < 8; j++) {
            o1[j] = accept ? xdv[j]  : xv[j];
            o2[j] = accept ? xdav[j] : xav[j];
        }
        #pragma unroll
        for (int h = 0; h < 2; h++) {
            *(float4*)&out[base + 4*h]      = *(float4*)&o1[4*h];
            *(float4*)&out[BD + base + 4*h] = *(float4*)&o2[4*h];
        }
        return;
    }

    if (accept) {
        #pragma unroll
        for (int h = 0; h < 2; h++) {
            *(float4*)&g_x [base + 4*h] = *(float4*)&xdv [4*h];
            *(float4*)&g_xa[base + 4*h] = *(float4*)&xdav[4*h];
            *(float4*)&g_vx[base + 4*h] = *(float4*)&vxdv[4*h];
            *(float4*)&g_p [base + 4*h] = *(float4*)&p2v [4*h];
        }
    }

    // Next proposal: p_next = accept ? p2 : p (bit-identical to recompute).
    float rrv[8], xdn[8];
    #pragma unroll
    for (int h = 0; h < 2; h++)
        *(float4*)&rrv[4*h] = __ldg((const float4*)&rr_next[base + 4*h]);
    #pragma unroll
    for (int j = 0; j < 8; j++) {
        float xn = accept ? xdv[j] : xv[j];
        float pn = accept ? p2v[j] : pv[j];
        float s  = 1.0f - 2.0f * xn;
        float ind = (rrv[j] < pn) ? 1.0f : 0.0f;
        xdn[j] = xn + ind * s;
    }
    #pragma unroll
    for (int h = 0; h < 2; h++)
        *(float4*)&g_xd[base + 4*h] = *(float4*)&xdn[4*h];
}

// ---------------------------------------------------------------------------
extern "C" void kernel_launch(void* const* d_in, const int* in_sizes, int n_in,
                              void* d_out, int out_size) {
    (void)in_sizes; (void)n_in; (void)out_size;
    const float* x_in  = (const float*)d_in[0];
    const float* xa_in = (const float*)d_in[1];
    const float* Wm    = (const float*)d_in[2];
    const float* bvec  = (const float*)d_in[3];
    const float* rr    = (const float*)d_in[4];
    const float* noise = (const float*)d_in[5];
    const float* u     = (const float*)d_in[6];
    float* out = (float*)d_out;

    kinit<<<BD / 256, 256>>>(x_in, xa_in);
    gemm32<<<B_ / TM, 256>>>(Wm, 0);                 // g_vx = x @ W
    phase1<<<BD / 256, 256>>>(rr, bvec);             // proposal for step 0
    for (int s = 0; s < NSTEPS_; s++) {
        gemm32<<<B_ / TM, 256>>>(Wm, 1);             // g_vxd = x_delta @ W
        int lastf = (s == NSTEPS_ - 1);
        phase2<<<B_ / 8, 256>>>(noise + (size_t)s * BD, u + (size_t)s * B_,
                                lastf ? (const float*)d_in[4]   // unused when last
                                      : rr + (size_t)(s + 1) * BD,
                                bvec, out, lastf);
    }
}